// round 2
// baseline (speedup 1.0000x reference)
#include <cuda_runtime.h>
#include <cstdint>
#include <cstddef>

#define NN   8192
#define FIN  256
#define FOUT 128
#define ALPHA_SLOPE 0.2f

#define PB_STRIDE 68         // P tile row stride (floats), 64x64 tile
#define BB_KT     1032       // B tile per-k-tile stride (floats): 128*8 + 8 pad

// ---------------- scratch (device globals: no allocation allowed) ------------
__device__ float g_Wh[(size_t)NN * FOUT];   // Wh, stored tf32-rounded
__device__ float g_f1[NN];
__device__ float g_f2[NN];

// ---------------- helpers ----------------------------------------------------
__device__ __forceinline__ float to_tf32(float x) {
    uint32_t u;
    asm("cvt.rna.tf32.f32 %0, %1;" : "=r"(u) : "f"(x));
    return __uint_as_float(u);
}

__device__ __forceinline__ void mma_tf32(float* c,
                                         uint32_t a0, uint32_t a1, uint32_t a2, uint32_t a3,
                                         uint32_t b0, uint32_t b1) {
    asm volatile(
        "mma.sync.aligned.m16n8k8.row.col.f32.tf32.tf32.f32 "
        "{%0,%1,%2,%3}, {%4,%5,%6,%7}, {%8,%9}, {%0,%1,%2,%3};\n"
        : "+f"(c[0]), "+f"(c[1]), "+f"(c[2]), "+f"(c[3])
        : "r"(a0), "r"(a1), "r"(a2), "r"(a3), "r"(b0), "r"(b1));
}

// ---------------- Kernel A: Wh = h@W, f1 = Wh@a1, f2 = Wh@a2 -----------------
// grid 128, block 256. Each block: 64 rows x 128 cols, K=256 in 4 chunks.
__global__ void __launch_bounds__(256) wh_kernel(const float* __restrict__ h,
                                                 const float* __restrict__ W,
                                                 const float* __restrict__ a) {
    __shared__ float hs[64][64];
    __shared__ float Ws[64][FOUT];

    const int t  = threadIdx.x;
    const int i0 = blockIdx.x * 64;
    const int tf = t & 31;      // lane: 4 output cols tf*4..tf*4+3
    const int ti = t >> 5;      // warp: 8 output rows ti*8..ti*8+7

    float acc[8][4];
#pragma unroll
    for (int r = 0; r < 8; ++r)
#pragma unroll
        for (int c = 0; c < 4; ++c) acc[r][c] = 0.f;

    for (int kc = 0; kc < 4; ++kc) {
        __syncthreads();
#pragma unroll
        for (int idx = t; idx < 1024; idx += 256) {     // h tile 64x64
            int row = idx >> 4, c = idx & 15;
            *(float4*)&hs[row][c * 4] =
                *(const float4*)&h[(size_t)(i0 + row) * FIN + kc * 64 + c * 4];
        }
#pragma unroll
        for (int idx = t; idx < 2048; idx += 256) {     // W tile 64x128
            int row = idx >> 5, c = idx & 31;
            *(float4*)&Ws[row][c * 4] =
                *(const float4*)&W[(size_t)(kc * 64 + row) * FOUT + c * 4];
        }
        __syncthreads();
#pragma unroll 8
        for (int k = 0; k < 64; ++k) {
            float4 wv = *(float4*)&Ws[k][tf * 4];
#pragma unroll
            for (int r = 0; r < 8; ++r) {
                float hv = hs[ti * 8 + r][k];
                acc[r][0] += hv * wv.x;
                acc[r][1] += hv * wv.y;
                acc[r][2] += hv * wv.z;
                acc[r][3] += hv * wv.w;
            }
        }
    }

    // f1/f2 via warp reduction (each warp owns 8 full rows)
    float4 a1v = *(const float4*)&a[tf * 4];
    float4 a2v = *(const float4*)&a[FOUT + tf * 4];
#pragma unroll
    for (int r = 0; r < 8; ++r) {
        float v1 = acc[r][0] * a1v.x + acc[r][1] * a1v.y + acc[r][2] * a1v.z + acc[r][3] * a1v.w;
        float v2 = acc[r][0] * a2v.x + acc[r][1] * a2v.y + acc[r][2] * a2v.z + acc[r][3] * a2v.w;
#pragma unroll
        for (int off = 16; off > 0; off >>= 1) {
            v1 += __shfl_xor_sync(0xffffffffu, v1, off);
            v2 += __shfl_xor_sync(0xffffffffu, v2, off);
        }
        if (tf == 0) {
            g_f1[i0 + ti * 8 + r] = v1;
            g_f2[i0 + ti * 8 + r] = v2;
        }
    }

    // store Wh pre-rounded to tf32 (values feed the tf32 MMA B operand)
#pragma unroll
    for (int r = 0; r < 8; ++r) {
        float4 o;
        o.x = to_tf32(acc[r][0]);
        o.y = to_tf32(acc[r][1]);
        o.z = to_tf32(acc[r][2]);
        o.w = to_tf32(acc[r][3]);
        *(float4*)&g_Wh[(size_t)(i0 + ti * 8 + r) * FOUT + tf * 4] = o;
    }
}

// ---------------- Kernel C: fused masked-softmax attention -------------------
// grid 128, block 256 (8 warps: wi=wid>>1 in 0..3, wf=wid&1).
// Block tile: 64 rows(i) x 128 cols(f); loop 128 j-tiles of 64.
__global__ void __launch_bounds__(256) gat_kernel(const int* __restrict__ adj,
                                                  float* __restrict__ out) {
    extern __shared__ float smem[];
    float* Pbuf = smem;                        // 64 * 68
    float* Bbuf = smem + 64 * PB_STRIDE;       // 8 * 1032
    float* Ssh  = Bbuf + 8 * BB_KT;            // 64

    const int t    = threadIdx.x;
    const int lane = t & 31;
    const int wid  = t >> 5;
    const int i0   = blockIdx.x * 64;
    const int ii   = t >> 2;    // P producer: row within tile
    const int c4   = t & 3;     // P producer: 16-col chunk
    const int wi   = wid >> 1;
    const int wf   = wid & 1;
    const int l4   = lane >> 2;
    const int lm   = lane & 3;

    const float f1i = g_f1[i0 + ii];
    if (t < 64) Ssh[t] = 0.f;

    float fragC[8][4];
#pragma unroll
    for (int nt = 0; nt < 8; ++nt)
#pragma unroll
        for (int c = 0; c < 4; ++c) fragC[nt][c] = 0.f;

#pragma unroll 1
    for (int jt = 0; jt < NN / 64; ++jt) {
        const int j0 = jt * 64;
        __syncthreads();   // previous MMA reads done before refill

        // ---- stage Wh tile (64 j x 128 f) into k-pair-interleaved B layout
        // B[k,f] -> Bbuf[(k>>3)*1032 + f*8 + (k&3)*2 + ((k>>2)&1)]
#pragma unroll
        for (int it = 0; it < 8; ++it) {
            int idx  = it * 256 + t;
            int jrow = idx & 63;
            int cf   = idx >> 6;
            float4 w = *(const float4*)&g_Wh[(size_t)(j0 + jrow) * FOUT + cf * 4];
            int kt = jrow >> 3, kl = jrow & 7;
            int base = kt * BB_KT + (cf * 4) * 8 + (kl & 3) * 2 + (kl >> 2);
            Bbuf[base]      = w.x;
            Bbuf[base + 8]  = w.y;
            Bbuf[base + 16] = w.z;
            Bbuf[base + 24] = w.w;
        }

        // ---- build P tile (64x64): p = adj ? exp(leakyrelu(f1+f2)) : 0
        const int4* arow = (const int4*)(adj + (size_t)(i0 + ii) * NN + j0 + c4 * 16);
        float psum = 0.f;
#pragma unroll
        for (int q4 = 0; q4 < 4; ++q4) {
            int4   av  = arow[q4];
            float4 f2v = *(const float4*)&g_f2[j0 + c4 * 16 + q4 * 4];
            float4 pv;
            {
                float s = f1i + f2v.x; s = fmaxf(s, ALPHA_SLOPE * s);
                pv.x = (av.x > 0) ? to_tf32(__expf(s)) : 0.f;
            }
            {
                float s = f1i + f2v.y; s = fmaxf(s, ALPHA_SLOPE * s);
                pv.y = (av.y > 0) ? to_tf32(__expf(s)) : 0.f;
            }
            {
                float s = f1i + f2v.z; s = fmaxf(s, ALPHA_SLOPE * s);
                pv.z = (av.z > 0) ? to_tf32(__expf(s)) : 0.f;
            }
            {
                float s = f1i + f2v.w; s = fmaxf(s, ALPHA_SLOPE * s);
                pv.w = (av.w > 0) ? to_tf32(__expf(s)) : 0.f;
            }
            psum += pv.x + pv.y + pv.z + pv.w;
            *(float4*)&Pbuf[ii * PB_STRIDE + c4 * 16 + q4 * 4] = pv;
        }
        // reduce the 4 producers of each row, single writer accumulates S
        psum += __shfl_xor_sync(0xffffffffu, psum, 1);
        psum += __shfl_xor_sync(0xffffffffu, psum, 2);
        if (c4 == 0) Ssh[ii] += psum;

        __syncthreads();

        // ---- MMA: 16x64 per warp, k=64 in 8 steps of 8
#pragma unroll
        for (int kt = 0; kt < 8; ++kt) {
            const float* pA = &Pbuf[(wi * 16 + l4) * PB_STRIDE + kt * 8 + lm];
            uint32_t a0 = __float_as_uint(pA[0]);
            uint32_t a2 = __float_as_uint(pA[4]);
            uint32_t a1 = __float_as_uint(pA[8 * PB_STRIDE]);
            uint32_t a3 = __float_as_uint(pA[8 * PB_STRIDE + 4]);
            const float* pB = &Bbuf[kt * BB_KT + (wf * 64 + l4) * 8 + lm * 2];
#pragma unroll
            for (int nt = 0; nt < 8; ++nt) {
                float2 bb = *(const float2*)&pB[nt * 64];
                mma_tf32(fragC[nt], a0, a1, a2, a3,
                         __float_as_uint(bb.x), __float_as_uint(bb.y));
            }
        }
    }

    __syncthreads();

    // ---- epilogue: normalize by row-sum, elu, store
    const float s0 = 1.f / Ssh[wi * 16 + l4];
    const float s1 = 1.f / Ssh[wi * 16 + l4 + 8];
    const int   r0 = i0 + wi * 16 + l4;
#pragma unroll
    for (int nt = 0; nt < 8; ++nt) {
        int n = wf * 64 + nt * 8 + lm * 2;
        float x0 = fragC[nt][0] * s0;
        float x1 = fragC[nt][1] * s0;
        float x2 = fragC[nt][2] * s1;
        float x3 = fragC[nt][3] * s1;
        out[(size_t)r0 * FOUT + n]           = (x0 > 0.f) ? x0 : expm1f(x0);
        out[(size_t)r0 * FOUT + n + 1]       = (x1 > 0.f) ? x1 : expm1f(x1);
        out[(size_t)(r0 + 8) * FOUT + n]     = (x2 > 0.f) ? x2 : expm1f(x2);
        out[(size_t)(r0 + 8) * FOUT + n + 1] = (x3 > 0.f) ? x3 : expm1f(x3);
    }
}

// ---------------- launch ------------------------------------------------------
extern "C" void kernel_launch(void* const* d_in, const int* in_sizes, int n_in,
                              void* d_out, int out_size) {
    const float* h   = (const float*)d_in[0];
    const int*   adj = (const int*)d_in[1];
    const float* W   = (const float*)d_in[2];
    const float* a   = (const float*)d_in[3];
    float*       out = (float*)d_out;

    wh_kernel<<<NN / 64, 256>>>(h, W, a);

    const int smem_bytes = (64 * PB_STRIDE + 8 * BB_KT + 64) * sizeof(float); // 50688
    cudaFuncSetAttribute(gat_kernel, cudaFuncAttributeMaxDynamicSharedMemorySize, smem_bytes);
    gat_kernel<<<NN / 64, 256, smem_bytes>>>(adj, out);
}

// round 4
// speedup vs baseline: 1.2845x; 1.2845x over previous
#include <cuda_runtime.h>
#include <cstdint>
#include <cstddef>

#define NN   8192
#define FIN  256
#define FOUT 128
#define ALPHA_SLOPE 0.2f

#define PB_STRIDE 68         // P tile row stride (floats), 64x64 tile
#define BB_KT     1032       // B tile per-k-tile stride (floats): 128*8 + 8 pad
#define P_FLOATS  (64 * PB_STRIDE)     // 4352
#define B_FLOATS  (8 * BB_KT)          // 8256
#define STAGE_FLOATS (P_FLOATS + B_FLOATS)

// ---------------- scratch (device globals: no allocation allowed) ------------
__device__ float g_Wh[(size_t)NN * FOUT];   // Wh, stored tf32-rounded
__device__ float g_f1[NN];
__device__ float g_f2[NN];

// ---------------- helpers ----------------------------------------------------
__device__ __forceinline__ float to_tf32(float x) {
    uint32_t u;
    asm("cvt.rna.tf32.f32 %0, %1;" : "=r"(u) : "f"(x));
    return __uint_as_float(u);
}

__device__ __forceinline__ void mma_tf32(float* c,
                                         uint32_t a0, uint32_t a1, uint32_t a2, uint32_t a3,
                                         uint32_t b0, uint32_t b1) {
    asm volatile(
        "mma.sync.aligned.m16n8k8.row.col.f32.tf32.tf32.f32 "
        "{%0,%1,%2,%3}, {%4,%5,%6,%7}, {%8,%9}, {%0,%1,%2,%3};\n"
        : "+f"(c[0]), "+f"(c[1]), "+f"(c[2]), "+f"(c[3])
        : "r"(a0), "r"(a1), "r"(a2), "r"(a3), "r"(b0), "r"(b1));
}

__device__ __forceinline__ float lrelu_exp(float s) {
    s = fmaxf(s, ALPHA_SLOPE * s);
    return __expf(s);
}

// ---------------- Kernel A: Wh = h@W, f1 = Wh@a1, f2 = Wh@a2 -----------------
__global__ void __launch_bounds__(256) wh_kernel(const float* __restrict__ h,
                                                 const float* __restrict__ W,
                                                 const float* __restrict__ a) {
    __shared__ float hs[64][64];
    __shared__ float Ws[64][FOUT];

    const int t  = threadIdx.x;
    const int i0 = blockIdx.x * 64;
    const int tf = t & 31;
    const int ti = t >> 5;

    float acc[8][4];
#pragma unroll
    for (int r = 0; r < 8; ++r)
#pragma unroll
        for (int c = 0; c < 4; ++c) acc[r][c] = 0.f;

    for (int kc = 0; kc < 4; ++kc) {
        __syncthreads();
#pragma unroll
        for (int idx = t; idx < 1024; idx += 256) {
            int row = idx >> 4, c = idx & 15;
            *(float4*)&hs[row][c * 4] =
                *(const float4*)&h[(size_t)(i0 + row) * FIN + kc * 64 + c * 4];
        }
#pragma unroll
        for (int idx = t; idx < 2048; idx += 256) {
            int row = idx >> 5, c = idx & 31;
            *(float4*)&Ws[row][c * 4] =
                *(const float4*)&W[(size_t)(kc * 64 + row) * FOUT + c * 4];
        }
        __syncthreads();
#pragma unroll 8
        for (int k = 0; k < 64; ++k) {
            float4 wv = *(float4*)&Ws[k][tf * 4];
#pragma unroll
            for (int r = 0; r < 8; ++r) {
                float hv = hs[ti * 8 + r][k];
                acc[r][0] += hv * wv.x;
                acc[r][1] += hv * wv.y;
                acc[r][2] += hv * wv.z;
                acc[r][3] += hv * wv.w;
            }
        }
    }

    float4 a1v = *(const float4*)&a[tf * 4];
    float4 a2v = *(const float4*)&a[FOUT + tf * 4];
#pragma unroll
    for (int r = 0; r < 8; ++r) {
        float v1 = acc[r][0] * a1v.x + acc[r][1] * a1v.y + acc[r][2] * a1v.z + acc[r][3] * a1v.w;
        float v2 = acc[r][0] * a2v.x + acc[r][1] * a2v.y + acc[r][2] * a2v.z + acc[r][3] * a2v.w;
#pragma unroll
        for (int off = 16; off > 0; off >>= 1) {
            v1 += __shfl_xor_sync(0xffffffffu, v1, off);
            v2 += __shfl_xor_sync(0xffffffffu, v2, off);
        }
        if (tf == 0) {
            g_f1[i0 + ti * 8 + r] = v1;
            g_f2[i0 + ti * 8 + r] = v2;
        }
    }

#pragma unroll
    for (int r = 0; r < 8; ++r) {
        float4 o;
        o.x = to_tf32(acc[r][0]);
        o.y = to_tf32(acc[r][1]);
        o.z = to_tf32(acc[r][2]);
        o.w = to_tf32(acc[r][3]);
        *(float4*)&g_Wh[(size_t)(i0 + ti * 8 + r) * FOUT + tf * 4] = o;
    }
}

// ---------------- Kernel C: fused masked-softmax attention -------------------
// grid 128, block 512 (16 warps). Block tile: 64 rows(i) x 128 cols(f).
// Warp grid: wi (M, 2) x wf (N, 4) x wk (K, 2); warp tile 32x32, k-split 2.
// Double-buffered smem stages + register prefetch of adj/Wh/f2.
__global__ void __launch_bounds__(512, 1) gat_kernel(const int* __restrict__ adj,
                                                     float* __restrict__ out) {
    extern __shared__ float smem[];
    float* Pst[2];
    float* Bst[2];
    Pst[0] = smem;
    Bst[0] = smem + P_FLOATS;
    Pst[1] = smem + STAGE_FLOATS;
    Bst[1] = smem + STAGE_FLOATS + P_FLOATS;
    float* Ssh = smem + 2 * STAGE_FLOATS;   // 64 floats

    const int t    = threadIdx.x;
    const int lane = t & 31;
    const int wid  = t >> 5;
    const int i0   = blockIdx.x * 64;

    // P producer mapping: each thread owns row ii, 8 cols starting c8*8
    const int ii = t >> 3;
    const int c8 = t & 7;

    // MMA warp mapping
    const int wi = wid >> 3;          // 0..1  (M)
    const int wf = (wid >> 1) & 3;    // 0..3  (N)
    const int wk = wid & 1;           // 0..1  (K split)
    const int l4 = lane >> 2;
    const int lm = lane & 3;

    const float f1i = g_f1[i0 + ii];

    float fragC[2][4][4];
#pragma unroll
    for (int mt = 0; mt < 2; ++mt)
#pragma unroll
        for (int nt = 0; nt < 4; ++nt)
#pragma unroll
            for (int c = 0; c < 4; ++c) fragC[mt][nt][c] = 0.f;

    // prefetch registers
    int4   adjA, adjB;
    float4 f2a, f2b;
    float4 whr[4];

    const int* adj_base = adj + (size_t)(i0 + ii) * NN + c8 * 8;

#define PREFETCH(J0)                                                            \
    do {                                                                        \
        const int _j0 = (J0);                                                   \
        adjA = *(const int4*)(adj_base + _j0);                                  \
        adjB = *(const int4*)(adj_base + _j0 + 4);                              \
        f2a  = *(const float4*)&g_f2[_j0 + c8 * 8];                             \
        f2b  = *(const float4*)&g_f2[_j0 + c8 * 8 + 4];                         \
        _Pragma("unroll")                                                       \
        for (int it = 0; it < 4; ++it) {                                        \
            int idx  = it * 512 + t;                                            \
            int jrow = idx & 63;                                                \
            int cf   = idx >> 6;                                                \
            whr[it]  = *(const float4*)&g_Wh[(size_t)(_j0 + jrow) * FOUT + cf * 4]; \
        }                                                                       \
    } while (0)

#define STORE_STAGE(PD, BD)                                                     \
    do {                                                                        \
        float4 pva, pvb;                                                        \
        pva.x = (adjA.x > 0) ? to_tf32(lrelu_exp(f1i + f2a.x)) : 0.f;           \
        pva.y = (adjA.y > 0) ? to_tf32(lrelu_exp(f1i + f2a.y)) : 0.f;           \
        pva.z = (adjA.z > 0) ? to_tf32(lrelu_exp(f1i + f2a.z)) : 0.f;           \
        pva.w = (adjA.w > 0) ? to_tf32(lrelu_exp(f1i + f2a.w)) : 0.f;           \
        pvb.x = (adjB.x > 0) ? to_tf32(lrelu_exp(f1i + f2b.x)) : 0.f;           \
        pvb.y = (adjB.y > 0) ? to_tf32(lrelu_exp(f1i + f2b.y)) : 0.f;           \
        pvb.z = (adjB.z > 0) ? to_tf32(lrelu_exp(f1i + f2b.z)) : 0.f;           \
        pvb.w = (adjB.w > 0) ? to_tf32(lrelu_exp(f1i + f2b.w)) : 0.f;           \
        *(float4*)&(PD)[ii * PB_STRIDE + c8 * 8]     = pva;                     \
        *(float4*)&(PD)[ii * PB_STRIDE + c8 * 8 + 4] = pvb;                     \
        float psum = pva.x + pva.y + pva.z + pva.w                              \
                   + pvb.x + pvb.y + pvb.z + pvb.w;                             \
        psum += __shfl_xor_sync(0xffffffffu, psum, 1);                          \
        psum += __shfl_xor_sync(0xffffffffu, psum, 2);                          \
        psum += __shfl_xor_sync(0xffffffffu, psum, 4);                          \
        if (c8 == 0) Ssh[ii] += psum;                                           \
        _Pragma("unroll")                                                       \
        for (int it = 0; it < 4; ++it) {                                        \
            int idx  = it * 512 + t;                                            \
            int jrow = idx & 63;                                                \
            int cf   = idx >> 6;                                                \
            int kt   = jrow >> 3, kl = jrow & 7;                                \
            int base = kt * BB_KT + (cf * 4) * 8 + (kl & 3) * 2 + (kl >> 2);    \
            (BD)[base]      = whr[it].x;                                        \
            (BD)[base + 8]  = whr[it].y;                                        \
            (BD)[base + 16] = whr[it].z;                                        \
            (BD)[base + 24] = whr[it].w;                                        \
        }                                                                       \
    } while (0)

    if (t < 64) Ssh[t] = 0.f;
    PREFETCH(0);
    __syncthreads();           // Ssh zero visible before first accumulate
    STORE_STAGE(Pst[0], Bst[0]);
    __syncthreads();

#pragma unroll 1
    for (int jt = 0; jt < NN / 64; ++jt) {
        const int cur = jt & 1;
        const bool has_next = (jt + 1) < NN / 64;
        if (has_next) PREFETCH((jt + 1) * 64);

        // ---- MMA on current stage: warp tile 32x32, kt range [wk*4, wk*4+4)
        const float* Pc = Pst[cur];
        const float* Bc = Bst[cur];
#pragma unroll
        for (int k2 = 0; k2 < 4; ++k2) {
            const int kt = wk * 4 + k2;
            const float* pA = &Pc[(wi * 32 + l4) * PB_STRIDE + kt * 8 + lm];
            uint32_t a0[2], a1[2], a2[2], a3[2];
#pragma unroll
            for (int mt = 0; mt < 2; ++mt) {
                const float* pAm = pA + mt * 16 * PB_STRIDE;
                a0[mt] = __float_as_uint(pAm[0]);
                a2[mt] = __float_as_uint(pAm[4]);
                a1[mt] = __float_as_uint(pAm[8 * PB_STRIDE]);
                a3[mt] = __float_as_uint(pAm[8 * PB_STRIDE + 4]);
            }
            const float* pB = &Bc[kt * BB_KT + (wf * 32 + l4) * 8 + lm * 2];
#pragma unroll
            for (int nt = 0; nt < 4; ++nt) {
                float2 bb = *(const float2*)&pB[nt * 64];
                uint32_t b0 = __float_as_uint(bb.x);
                uint32_t b1 = __float_as_uint(bb.y);
#pragma unroll
                for (int mt = 0; mt < 2; ++mt)
                    mma_tf32(fragC[mt][nt], a0[mt], a1[mt], a2[mt], a3[mt], b0, b1);
            }
        }

        if (has_next) STORE_STAGE(Pst[cur ^ 1], Bst[cur ^ 1]);
        __syncthreads();
    }

    // ---- epilogue: combine k-split partials, normalize, elu, store ----------
    float* red = smem;   // 8 tiles x 1024 floats = 8192 floats (fits in stage 0)
    const int rbase = (wi * 4 + wf) * 1024;
    if (wk == 1) {
#pragma unroll
        for (int mt = 0; mt < 2; ++mt)
#pragma unroll
            for (int nt = 0; nt < 4; ++nt) {
                int r = mt * 16 + l4, c = nt * 8 + lm * 2;
                red[rbase + r * 32 + c]           = fragC[mt][nt][0];
                red[rbase + r * 32 + c + 1]       = fragC[mt][nt][1];
                red[rbase + (r + 8) * 32 + c]     = fragC[mt][nt][2];
                red[rbase + (r + 8) * 32 + c + 1] = fragC[mt][nt][3];
            }
    }
    __syncthreads();
    if (wk == 0) {
#pragma unroll
        for (int mt = 0; mt < 2; ++mt) {
            const int row0 = wi * 32 + mt * 16 + l4;
            const float s0 = 1.f / Ssh[row0];
            const float s1 = 1.f / Ssh[row0 + 8];
#pragma unroll
            for (int nt = 0; nt < 4; ++nt) {
                int r = mt * 16 + l4, c = nt * 8 + lm * 2;
                float x0 = (fragC[mt][nt][0] + red[rbase + r * 32 + c])           * s0;
                float x1 = (fragC[mt][nt][1] + red[rbase + r * 32 + c + 1])       * s0;
                float x2 = (fragC[mt][nt][2] + red[rbase + (r + 8) * 32 + c])     * s1;
                float x3 = (fragC[mt][nt][3] + red[rbase + (r + 8) * 32 + c + 1]) * s1;
                const int gcol = wf * 32 + nt * 8 + lm * 2;
                const size_t o0 = (size_t)(i0 + row0) * FOUT + gcol;
                const size_t o1 = (size_t)(i0 + row0 + 8) * FOUT + gcol;
                out[o0]     = (x0 > 0.f) ? x0 : expm1f(x0);
                out[o0 + 1] = (x1 > 0.f) ? x1 : expm1f(x1);
                out[o1]     = (x2 > 0.f) ? x2 : expm1f(x2);
                out[o1 + 1] = (x3 > 0.f) ? x3 : expm1f(x3);
            }
        }
    }
#undef PREFETCH
#undef STORE_STAGE
}

// ---------------- launch ------------------------------------------------------
extern "C" void kernel_launch(void* const* d_in, const int* in_sizes, int n_in,
                              void* d_out, int out_size) {
    const float* h   = (const float*)d_in[0];
    const int*   adj = (const int*)d_in[1];
    const float* W   = (const float*)d_in[2];
    const float* a   = (const float*)d_in[3];
    float*       out = (float*)d_out;

    wh_kernel<<<NN / 64, 256>>>(h, W, a);

    const int smem_bytes = (2 * STAGE_FLOATS + 64) * sizeof(float);  // 101376 B
    cudaFuncSetAttribute(gat_kernel, cudaFuncAttributeMaxDynamicSharedMemorySize, smem_bytes);
    gat_kernel<<<NN / 64, 512, smem_bytes>>>(adj, out);
}

// round 5
// speedup vs baseline: 1.4011x; 1.0907x over previous
#include <cuda_runtime.h>
#include <cstdint>
#include <cstddef>

#define NN   8192
#define FIN  256
#define FOUT 128
#define ALPHA_SLOPE 0.2f

#define PB_STRIDE 68                   // P tile row stride (floats)
#define BB_KT     1024                 // B per-k-tile stride (contiguous now)
#define P_FLOATS  (64 * PB_STRIDE)     // 4352
#define B_FLOATS  (8 * BB_KT)          // 8192
#define STAGE_FLOATS (P_FLOATS + B_FLOATS)   // 12544

// ---------------- scratch (device globals: no allocation allowed) ------------
// g_WhB: Wh pre-staged in MMA-B layout, per 64-row j-tile (8192 floats each):
//   addr = tile*8192 + kt*1024 + f*8 + (kl&3)*2 + (kl>>2),  row = tile*64+kt*8+kl
__device__ float g_WhB[(size_t)NN * FOUT];
__device__ float g_f1[NN];
__device__ float g_f2[NN];

// ---------------- helpers ----------------------------------------------------
__device__ __forceinline__ float to_tf32(float x) {
    uint32_t u;
    asm("cvt.rna.tf32.f32 %0, %1;" : "=r"(u) : "f"(x));
    return __uint_as_float(u);
}

__device__ __forceinline__ void mma_tf32(float* c,
                                         uint32_t a0, uint32_t a1, uint32_t a2, uint32_t a3,
                                         uint32_t b0, uint32_t b1) {
    asm volatile(
        "mma.sync.aligned.m16n8k8.row.col.f32.tf32.tf32.f32 "
        "{%0,%1,%2,%3}, {%4,%5,%6,%7}, {%8,%9}, {%0,%1,%2,%3};\n"
        : "+f"(c[0]), "+f"(c[1]), "+f"(c[2]), "+f"(c[3])
        : "r"(a0), "r"(a1), "r"(a2), "r"(a3), "r"(b0), "r"(b1));
}

__device__ __forceinline__ float lrelu_exp(float s) {
    s = fmaxf(s, ALPHA_SLOPE * s);
    return __expf(s);
}

__device__ __forceinline__ void cp_async16(uint32_t smem_dst, const void* gsrc) {
    asm volatile("cp.async.cg.shared.global [%0], [%1], 16;\n"
                 :: "r"(smem_dst), "l"(gsrc));
}
__device__ __forceinline__ void cp_async_commit() {
    asm volatile("cp.async.commit_group;\n");
}
__device__ __forceinline__ void cp_async_wait0() {
    asm volatile("cp.async.wait_group 0;\n");
}

// ---------------- Kernel A: Wh = h@W (stored in B layout), f1, f2 ------------
__global__ void __launch_bounds__(256) wh_kernel(const float* __restrict__ h,
                                                 const float* __restrict__ W,
                                                 const float* __restrict__ a) {
    __shared__ float hs[64][64];
    __shared__ float Ws[64][FOUT];

    const int t  = threadIdx.x;
    const int i0 = blockIdx.x * 64;
    const int tf = t & 31;      // 4 output cols tf*4..+3
    const int ti = t >> 5;      // 8 output rows ti*8..+7  (kt = ti, kl = r)

    float acc[8][4];
#pragma unroll
    for (int r = 0; r < 8; ++r)
#pragma unroll
        for (int c = 0; c < 4; ++c) acc[r][c] = 0.f;

    for (int kc = 0; kc < 4; ++kc) {
        __syncthreads();
#pragma unroll
        for (int idx = t; idx < 1024; idx += 256) {
            int row = idx >> 4, c = idx & 15;
            *(float4*)&hs[row][c * 4] =
                *(const float4*)&h[(size_t)(i0 + row) * FIN + kc * 64 + c * 4];
        }
#pragma unroll
        for (int idx = t; idx < 2048; idx += 256) {
            int row = idx >> 5, c = idx & 31;
            *(float4*)&Ws[row][c * 4] =
                *(const float4*)&W[(size_t)(kc * 64 + row) * FOUT + c * 4];
        }
        __syncthreads();
#pragma unroll 8
        for (int k = 0; k < 64; ++k) {
            float4 wv = *(float4*)&Ws[k][tf * 4];
#pragma unroll
            for (int r = 0; r < 8; ++r) {
                float hv = hs[ti * 8 + r][k];
                acc[r][0] += hv * wv.x;
                acc[r][1] += hv * wv.y;
                acc[r][2] += hv * wv.z;
                acc[r][3] += hv * wv.w;
            }
        }
    }

    float4 a1v = *(const float4*)&a[tf * 4];
    float4 a2v = *(const float4*)&a[FOUT + tf * 4];
#pragma unroll
    for (int r = 0; r < 8; ++r) {
        float v1 = acc[r][0] * a1v.x + acc[r][1] * a1v.y + acc[r][2] * a1v.z + acc[r][3] * a1v.w;
        float v2 = acc[r][0] * a2v.x + acc[r][1] * a2v.y + acc[r][2] * a2v.z + acc[r][3] * a2v.w;
#pragma unroll
        for (int off = 16; off > 0; off >>= 1) {
            v1 += __shfl_xor_sync(0xffffffffu, v1, off);
            v2 += __shfl_xor_sync(0xffffffffu, v2, off);
        }
        if (tf == 0) {
            g_f1[i0 + ti * 8 + r] = v1;
            g_f2[i0 + ti * 8 + r] = v2;
        }
    }

    // store into B-staged layout: slot (kl&3)*2 + (kl>>2); rows r and r+4 pair
    // into consecutive floats -> one STG.64 each
    float* base = &g_WhB[(size_t)blockIdx.x * 8192 + ti * 1024];
#pragma unroll
    for (int r = 0; r < 4; ++r) {
#pragma unroll
        for (int c = 0; c < 4; ++c) {
            float2 v;
            v.x = to_tf32(acc[r][c]);       // kl = r     -> slot 2r
            v.y = to_tf32(acc[r + 4][c]);   // kl = r + 4 -> slot 2r+1
            *(float2*)&base[(tf * 4 + c) * 8 + r * 2] = v;
        }
    }
}

// ---------------- Kernel C: fused masked-softmax attention -------------------
// grid 128, block 512 (16 warps). Block tile 64(i) x 128(f), j-tiles of 64.
// Warp grid: wi(M,2) x wf(N,4) x wk(K,2), warp tile 32x32.
// Double-buffered smem; B tiles via cp.async; adj/f2 register-prefetched;
// row-sums accumulated in registers, reduced once at the end.
__global__ void __launch_bounds__(512, 1) gat_kernel(const int* __restrict__ adj,
                                                     float* __restrict__ out) {
    extern __shared__ float smem[];
    float* Pst[2];
    float* Bst[2];
    Pst[0] = smem;
    Bst[0] = smem + P_FLOATS;
    Pst[1] = smem + STAGE_FLOATS;
    Bst[1] = smem + STAGE_FLOATS + P_FLOATS;
    float* Ssh = smem + 2 * STAGE_FLOATS;   // 64 floats

    const int t    = threadIdx.x;
    const int lane = t & 31;
    const int wid  = t >> 5;
    const int i0   = blockIdx.x * 64;

    const int ii = t >> 3;            // P producer row
    const int c8 = t & 7;             // P producer 8-col chunk

    const int wi = wid >> 3;
    const int wf = (wid >> 1) & 3;
    const int wk = wid & 1;
    const int l4 = lane >> 2;
    const int lm = lane & 3;

    const float f1i = g_f1[i0 + ii];
    float sacc = 0.f;                 // register row-sum partial

    float fragC[2][4][4];
#pragma unroll
    for (int mt = 0; mt < 2; ++mt)
#pragma unroll
        for (int nt = 0; nt < 4; ++nt)
#pragma unroll
            for (int c = 0; c < 4; ++c) fragC[mt][nt][c] = 0.f;

    // invariant addresses
    const int* adj_base = adj + (size_t)(i0 + ii) * NN + c8 * 8;
    const float* whb_base = g_WhB + (size_t)t * 16;          // cp.async src lane
    uint32_t bdst[2];
    bdst[0] = (uint32_t)__cvta_generic_to_shared(Bst[0]) + t * 64;  // 16 floats
    bdst[1] = (uint32_t)__cvta_generic_to_shared(Bst[1]) + t * 64;
    float* pdst[2];
    pdst[0] = &Pst[0][ii * PB_STRIDE + c8 * 8];
    pdst[1] = &Pst[1][ii * PB_STRIDE + c8 * 8];

    int4   adjA, adjB;
    float4 f2a, f2b;

#define PREFETCH(J0)                                                   \
    do {                                                               \
        const int _j0 = (J0);                                          \
        adjA = *(const int4*)(adj_base + _j0);                         \
        adjB = *(const int4*)(adj_base + _j0 + 4);                     \
        f2a  = *(const float4*)&g_f2[_j0 + c8 * 8];                    \
        f2b  = *(const float4*)&g_f2[_j0 + c8 * 8 + 4];                \
    } while (0)

#define CPASYNC_B(JT, ST)                                              \
    do {                                                               \
        const float* src = whb_base + (size_t)(JT) * 8192;             \
        uint32_t dst = bdst[ST];                                       \
        cp_async16(dst,       src);                                    \
        cp_async16(dst + 16,  src + 4);                                \
        cp_async16(dst + 32,  src + 8);                                \
        cp_async16(dst + 48,  src + 12);                               \
        cp_async_commit();                                             \
    } while (0)

#define STORE_P(ST)                                                    \
    do {                                                               \
        float4 pva, pvb;                                               \
        pva.x = (adjA.x > 0) ? to_tf32(lrelu_exp(f1i + f2a.x)) : 0.f;  \
        pva.y = (adjA.y > 0) ? to_tf32(lrelu_exp(f1i + f2a.y)) : 0.f;  \
        pva.z = (adjA.z > 0) ? to_tf32(lrelu_exp(f1i + f2a.z)) : 0.f;  \
        pva.w = (adjA.w > 0) ? to_tf32(lrelu_exp(f1i + f2a.w)) : 0.f;  \
        pvb.x = (adjB.x > 0) ? to_tf32(lrelu_exp(f1i + f2b.x)) : 0.f;  \
        pvb.y = (adjB.y > 0) ? to_tf32(lrelu_exp(f1i + f2b.y)) : 0.f;  \
        pvb.z = (adjB.z > 0) ? to_tf32(lrelu_exp(f1i + f2b.z)) : 0.f;  \
        pvb.w = (adjB.w > 0) ? to_tf32(lrelu_exp(f1i + f2b.w)) : 0.f;  \
        *(float4*)(pdst[ST])     = pva;                                \
        *(float4*)(pdst[ST] + 4) = pvb;                                \
        sacc += pva.x + pva.y + pva.z + pva.w                          \
              + pvb.x + pvb.y + pvb.z + pvb.w;                         \
    } while (0)

    // prologue: fill stage 0
    CPASYNC_B(0, 0);
    PREFETCH(0);
    STORE_P(0);
    cp_async_wait0();
    __syncthreads();

#pragma unroll 1
    for (int jt = 0; jt < NN / 64; ++jt) {
        const int cur = jt & 1;
        const bool has_next = (jt + 1) < NN / 64;
        if (has_next) {
            CPASYNC_B(jt + 1, cur ^ 1);
            PREFETCH((jt + 1) * 64);
        }

        // ---- MMA on current stage
        const float* Pc = Pst[cur];
        const float* Bc = Bst[cur];
#pragma unroll
        for (int k2 = 0; k2 < 4; ++k2) {
            const int kt = wk * 4 + k2;
            const float* pA = &Pc[(wi * 32 + l4) * PB_STRIDE + kt * 8 + lm];
            uint32_t a0[2], a1[2], a2[2], a3[2];
#pragma unroll
            for (int mt = 0; mt < 2; ++mt) {
                const float* pAm = pA + mt * 16 * PB_STRIDE;
                a0[mt] = __float_as_uint(pAm[0]);
                a2[mt] = __float_as_uint(pAm[4]);
                a1[mt] = __float_as_uint(pAm[8 * PB_STRIDE]);
                a3[mt] = __float_as_uint(pAm[8 * PB_STRIDE + 4]);
            }
            const float* pB = &Bc[kt * BB_KT + (wf * 32 + l4) * 8 + lm * 2];
#pragma unroll
            for (int nt = 0; nt < 4; ++nt) {
                float2 bb = *(const float2*)&pB[nt * 64];
                uint32_t b0 = __float_as_uint(bb.x);
                uint32_t b1 = __float_as_uint(bb.y);
#pragma unroll
                for (int mt = 0; mt < 2; ++mt)
                    mma_tf32(fragC[mt][nt], a0[mt], a1[mt], a2[mt], a3[mt], b0, b1);
            }
        }

        if (has_next) STORE_P(cur ^ 1);
        cp_async_wait0();
        __syncthreads();
    }

    // ---- final row-sum reduction (across c8 within each warp) ---------------
    sacc += __shfl_xor_sync(0xffffffffu, sacc, 1);
    sacc += __shfl_xor_sync(0xffffffffu, sacc, 2);
    sacc += __shfl_xor_sync(0xffffffffu, sacc, 4);
    if (c8 == 0) Ssh[ii] = sacc;

    // ---- epilogue: combine k-split partials, normalize, elu, store ----------
    float* red = smem;                        // reuse stage 0 region
    const int rbase = (wi * 4 + wf) * 1024;
    if (wk == 1) {
#pragma unroll
        for (int mt = 0; mt < 2; ++mt)
#pragma unroll
            for (int nt = 0; nt < 4; ++nt) {
                int r = mt * 16 + l4, c = nt * 8 + lm * 2;
                red[rbase + r * 32 + c]           = fragC[mt][nt][0];
                red[rbase + r * 32 + c + 1]       = fragC[mt][nt][1];
                red[rbase + (r + 8) * 32 + c]     = fragC[mt][nt][2];
                red[rbase + (r + 8) * 32 + c + 1] = fragC[mt][nt][3];
            }
    }
    __syncthreads();
    if (wk == 0) {
#pragma unroll
        for (int mt = 0; mt < 2; ++mt) {
            const int row0 = wi * 32 + mt * 16 + l4;
            const float s0 = 1.f / Ssh[row0];
            const float s1 = 1.f / Ssh[row0 + 8];
#pragma unroll
            for (int nt = 0; nt < 4; ++nt) {
                int r = mt * 16 + l4, c = nt * 8 + lm * 2;
                float x0 = (fragC[mt][nt][0] + red[rbase + r * 32 + c])           * s0;
                float x1 = (fragC[mt][nt][1] + red[rbase + r * 32 + c + 1])       * s0;
                float x2 = (fragC[mt][nt][2] + red[rbase + (r + 8) * 32 + c])     * s1;
                float x3 = (fragC[mt][nt][3] + red[rbase + (r + 8) * 32 + c + 1]) * s1;
                const int gcol = wf * 32 + nt * 8 + lm * 2;
                const size_t o0 = (size_t)(i0 + row0) * FOUT + gcol;
                const size_t o1 = (size_t)(i0 + row0 + 8) * FOUT + gcol;
                out[o0]     = (x0 > 0.f) ? x0 : expm1f(x0);
                out[o0 + 1] = (x1 > 0.f) ? x1 : expm1f(x1);
                out[o1]     = (x2 > 0.f) ? x2 : expm1f(x2);
                out[o1 + 1] = (x3 > 0.f) ? x3 : expm1f(x3);
            }
        }
    }
#undef PREFETCH
#undef CPASYNC_B
#undef STORE_P
}

// ---------------- launch ------------------------------------------------------
extern "C" void kernel_launch(void* const* d_in, const int* in_sizes, int n_in,
                              void* d_out, int out_size) {
    const float* h   = (const float*)d_in[0];
    const int*   adj = (const int*)d_in[1];
    const float* W   = (const float*)d_in[2];
    const float* a   = (const float*)d_in[3];
    float*       out = (float*)d_out;

    wh_kernel<<<NN / 64, 256>>>(h, W, a);

    const int smem_bytes = (2 * STAGE_FLOATS + 64) * sizeof(float);  // 100608 B
    cudaFuncSetAttribute(gat_kernel, cudaFuncAttributeMaxDynamicSharedMemorySize, smem_bytes);
    gat_kernel<<<NN / 64, 512, smem_bytes>>>(adj, out);
}